// round 9
// baseline (speedup 1.0000x reference)
#include <cuda_runtime.h>
#include <cuda_fp16.h>

// APPNP, K=10. State g = norm ⊙ h kept in fp16 (row = 64 halves = 128B).
//   g_{t+1} = 0.9*norm^2 * (sum_{(s->v)} g_t[s]) + anchor,  anchor = 0.1*norm*feat
// Final: h = 0.9*norm*agg + 0.1*feat (fp32).
//
// Round 9: all 10 propagation iterations fused into ONE persistent kernel
// with a software grid barrier (grid sized to guaranteed co-residency via the
// occupancy API). Removes 9 launch/ramp/tail overheads and keeps L1D warm
// across iterations (per-launch L1 flush no longer wipes g_srcs/rowptr).
// Gather body unchanged from round 8 (SIMT-4: one LDG.128 = four 128B rows).

#define NMAX  100000
#define DF    64
#define DF2   (DF / 2)
#define EMAX  1000000
#define EPAD  (EMAX + 4 * NMAX + 32)
#define KITER 10
#define TILE  256
#define NTILE ((NMAX + TILE - 1) / TILE)   // 391

__device__ uint4 g_a[(NMAX + 1) * 8];
__device__ uint4 g_b[(NMAX + 1) * 8];
__device__ uint4 g_anchor[(NMAX + 1) * 8];  // 0.1*norm*feat in fp16
__device__ float g_norm[NMAX];
__device__ int   g_deg[NMAX];
__device__ int   g_rowptr[NMAX + 1];        // padded-degree prefix
__device__ int   g_cursor[NMAX];
__device__ int   g_srcs[EPAD];
__device__ int   g_part[NTILE];

// grid barrier state
__device__ int          g_bar_cnt = 0;
__device__ volatile int g_bar_gen = 0;

// ---------------------------------------------------------------- build ----

__global__ void k_zero(int n) {
    int i = blockIdx.x * blockDim.x + threadIdx.x;
    if (i < n) { g_deg[i] = 0; g_cursor[i] = 0; }
}

__global__ void k_deg(const int* __restrict__ dst, int e) {
    int i = blockIdx.x * blockDim.x + threadIdx.x;
    if (i < e) atomicAdd(&g_deg[dst[i]], 1);
}

__global__ void k_scan_part(int n) {
    __shared__ int sh[TILE];
    int t = threadIdx.x;
    int i = blockIdx.x * TILE + t;
    int d = (i < n) ? g_deg[i] : 0;
    sh[t] = (d + 3) & ~3;
    __syncthreads();
    for (int off = TILE >> 1; off > 0; off >>= 1) {
        if (t < off) sh[t] += sh[t + off];
        __syncthreads();
    }
    if (t == 0) g_part[blockIdx.x] = sh[0];
}

__global__ void k_scan_top(int nb) {
    __shared__ int sh[512];
    int t = threadIdx.x;
    int v = (t < nb) ? g_part[t] : 0;
    sh[t] = v;
    __syncthreads();
    for (int off = 1; off < 512; off <<= 1) {
        int x = (t >= off) ? sh[t - off] : 0;
        __syncthreads();
        sh[t] += x;
        __syncthreads();
    }
    if (t < nb) g_part[t] = sh[t] - v;
}

__global__ void k_scan_fin(int n) {
    __shared__ int sh[TILE];
    int t = threadIdx.x;
    int i = blockIdx.x * TILE + t;
    int d    = (i < n) ? g_deg[i] : 0;
    int dpad = (d + 3) & ~3;
    sh[t] = dpad;
    __syncthreads();
    for (int off = 1; off < TILE; off <<= 1) {
        int x = (t >= off) ? sh[t - off] : 0;
        __syncthreads();
        sh[t] += x;
        __syncthreads();
    }
    if (i < n) {
        g_rowptr[i] = sh[t] - dpad + g_part[blockIdx.x];
        g_norm[i]   = rsqrtf(fmaxf((float)d, 1.0f));
        if (i == n - 1) g_rowptr[n] = sh[t] + g_part[blockIdx.x];
    }
}

__global__ void k_fill(const int* __restrict__ src,
                       const int* __restrict__ dst, int e) {
    int i = blockIdx.x * blockDim.x + threadIdx.x;
    if (i < e) {
        int d = dst[i];
        int pos = g_rowptr[d] + atomicAdd(&g_cursor[d], 1);
        g_srcs[pos] = src[i];
    }
}

__global__ void k_pad(int n) {
    int i = blockIdx.x * blockDim.x + threadIdx.x;
    if (i < n) {
        int s  = g_rowptr[i] + g_deg[i];
        int e2 = g_rowptr[i + 1];
        for (int j = s; j < e2; ++j) g_srcs[j] = n;
    }
}

__global__ void k_init(const float* __restrict__ feat, int n) {
    int i = blockIdx.x * blockDim.x + threadIdx.x;   // half2 index
    int tot = (n + 1) * DF2;
    if (i >= tot) return;
    __half2* pa = reinterpret_cast<__half2*>(g_a);
    __half2* pb = reinterpret_cast<__half2*>(g_b);
    __half2* pn = reinterpret_cast<__half2*>(g_anchor);
    int row = i >> 5;
    if (row < n) {
        float nm = g_norm[row];
        float2 f = reinterpret_cast<const float2*>(feat)[i];
        pa[i] = __floats2half2_rn(nm * f.x, nm * f.y);
        pn[i] = __floats2half2_rn(0.1f * nm * f.x, 0.1f * nm * f.y);
    } else {
        __half2 z = __floats2half2_rn(0.f, 0.f);
        pa[i] = z; pb[i] = z; pn[i] = z;
    }
}

// ----------------------------------------------------------------- loop ----

__device__ __forceinline__ void acc_row(const uint4& r, float* acc) {
    const __half2* h = reinterpret_cast<const __half2*>(&r);
    #pragma unroll
    for (int j = 0; j < 4; ++j) {
        float2 w = __half22float2(h[j]);
        acc[2 * j]     += w.x;
        acc[2 * j + 1] += w.y;
    }
}

// All-blocks-resident grid barrier (grid sized via occupancy API).
__device__ __forceinline__ void grid_barrier(int nblocks) {
    __syncthreads();
    if (threadIdx.x == 0) {
        int gen = g_bar_gen;
        __threadfence();
        if (atomicAdd(&g_bar_cnt, 1) == nblocks - 1) {
            g_bar_cnt = 0;
            __threadfence();
            g_bar_gen = gen + 1;
        } else {
            while (g_bar_gen == gen) { __nanosleep(64); }
            __threadfence();
        }
    }
    __syncthreads();
}

// Persistent: all KITER iterations in one launch. One warp per node per
// iteration pass; warps stride over nodes. SIMT-4 gather (4 rows / LDG.128).
__global__ void __launch_bounds__(256) k_prop_persist(
        const float* __restrict__ feat, float* __restrict__ out,
        int n, int nblocks) {
    int warps_total = (nblocks * (int)blockDim.x) >> 5;
    int wid0 = (blockIdx.x * blockDim.x + threadIdx.x) >> 5;
    int lane = threadIdx.x & 31;
    int slot = lane >> 3;
    int oct  = lane & 7;

    for (int t = 0; t < KITER; ++t) {
        const uint4* gin  = (t & 1) ? g_b : g_a;
        uint4*       gout = (t & 1) ? g_a : g_b;
        bool last = (t == KITER - 1);

        for (int v = wid0; v < n; v += warps_total) {
            int idx = __ldg(&g_rowptr[v]);
            int end = __ldg(&g_rowptr[v + 1]);   // padded to multiple of 4

            float acc[8];
            #pragma unroll
            for (int j = 0; j < 8; ++j) acc[j] = 0.f;

            for (; idx + 8 <= end; idx += 8) {
                int s0 = __ldg(&g_srcs[idx + slot]);
                int s1 = __ldg(&g_srcs[idx + 4 + slot]);
                uint4 r0 = gin[s0 * 8 + oct];
                uint4 r1 = gin[s1 * 8 + oct];
                acc_row(r0, acc);
                acc_row(r1, acc);
            }
            if (idx < end) {
                int s0 = __ldg(&g_srcs[idx + slot]);
                uint4 r0 = gin[s0 * 8 + oct];
                acc_row(r0, acc);
            }

            #pragma unroll
            for (int j = 0; j < 8; ++j) {
                acc[j] += __shfl_xor_sync(0xffffffff, acc[j], 8);
                acc[j] += __shfl_xor_sync(0xffffffff, acc[j], 16);
            }

            float nm = __ldg(&g_norm[v]);

            if (!last) {
                if (lane < 8) {
                    float c1 = 0.9f * nm * nm;
                    uint4 an = g_anchor[v * 8 + oct];
                    const __half2* ah = reinterpret_cast<const __half2*>(&an);
                    uint4 o;
                    __half2* oh = reinterpret_cast<__half2*>(&o);
                    #pragma unroll
                    for (int j = 0; j < 4; ++j) {
                        float2 a2 = __half22float2(ah[j]);
                        oh[j] = __floats2half2_rn(c1 * acc[2 * j]     + a2.x,
                                                  c1 * acc[2 * j + 1] + a2.y);
                    }
                    gout[v * 8 + oct] = o;
                }
            } else {
                if (lane < 8) {
                    float c1 = 0.9f * nm;
                    const float4* fr = reinterpret_cast<const float4*>(feat + v * DF);
                    float4* orow = reinterpret_cast<float4*>(out + v * DF);
                    float4 f0 = fr[oct * 2];
                    float4 f1 = fr[oct * 2 + 1];
                    float4 o0, o1;
                    o0.x = c1 * acc[0] + 0.1f * f0.x;
                    o0.y = c1 * acc[1] + 0.1f * f0.y;
                    o0.z = c1 * acc[2] + 0.1f * f0.z;
                    o0.w = c1 * acc[3] + 0.1f * f0.w;
                    o1.x = c1 * acc[4] + 0.1f * f1.x;
                    o1.y = c1 * acc[5] + 0.1f * f1.y;
                    o1.z = c1 * acc[6] + 0.1f * f1.z;
                    o1.w = c1 * acc[7] + 0.1f * f1.w;
                    orow[oct * 2]     = o0;
                    orow[oct * 2 + 1] = o1;
                }
            }
        }

        if (t != KITER - 1) grid_barrier(nblocks);
    }
}

// ---------------------------------------------------------------- launch ----

extern "C" void kernel_launch(void* const* d_in, const int* in_sizes, int n_in,
                              void* d_out, int out_size) {
    const float* feat = (const float*)d_in[0];
    const int*   src  = (const int*)d_in[1];
    const int*   dst  = (const int*)d_in[2];
    float*       out  = (float*)d_out;

    int n = in_sizes[0] / DF;   // 100000
    int e = in_sizes[1];        // 1000000

    const int T = 256;
    int blk_n = (n + T - 1) / T;
    int blk_e = (e + T - 1) / T;
    int blk_i = ((n + 1) * DF2 + T - 1) / T;
    int nb    = (n + TILE - 1) / TILE;

    // CSR build with 4-padded segments
    k_zero<<<blk_n, T>>>(n);
    k_deg<<<blk_e, T>>>(dst, e);
    k_scan_part<<<nb, TILE>>>(n);
    k_scan_top<<<1, 512>>>(nb);
    k_scan_fin<<<nb, TILE>>>(n);
    k_fill<<<blk_e, T>>>(src, dst, e);
    k_pad<<<blk_n, T>>>(n);
    k_init<<<blk_i, T>>>(feat, n);

    // Persistent propagation: grid sized so every block is co-resident
    // (required for the software grid barrier).
    int dev = 0;
    cudaGetDevice(&dev);
    int sm_count = 0;
    cudaDeviceGetAttribute(&sm_count, cudaDevAttrMultiProcessorCount, dev);
    int occ = 0;
    cudaOccupancyMaxActiveBlocksPerMultiprocessor(&occ, k_prop_persist, T, 0);
    if (occ < 1) occ = 1;
    int nblocks = sm_count * occ;
    int max_useful = (n * 32 + T - 1) / T;   // no more warps than nodes
    if (nblocks > max_useful) nblocks = max_useful;

    k_prop_persist<<<nblocks, T>>>(feat, out, n, nblocks);
}

// round 10
// speedup vs baseline: 1.0561x; 1.0561x over previous
#include <cuda_runtime.h>
#include <cuda_fp16.h>

// APPNP, K=10. State g = norm ⊙ h kept in fp16 (row = 64 halves = 128B).
//   g_{t+1} = 0.9*norm^2 * (sum_{(s->v)} g_t[s]) + anchor,  anchor = 0.1*norm*feat
// Final: h = 0.9*norm*agg + 0.1*feat (fp32).
//
// Round 10: SINGLE-WAVE grid-stride k_prop. The ~22us/iter floor matched the
// multi-wave launch model (12500 tiny blocks -> ~10.5 waves x (T_CTA +
// T_wave_trans)), not bytes or instructions. Now: nblocks = SMs x occupancy,
// each warp strides over nodes -> n_waves = 1, cross-node loads overlap
// within the warp's loop. Gather body unchanged (SIMT-4 fp16 rows).

#define NMAX  100000
#define DF    64
#define DF2   (DF / 2)
#define EMAX  1000000
#define EPAD  (EMAX + 4 * NMAX + 32)
#define KITER 10
#define TILE  256
#define NTILE ((NMAX + TILE - 1) / TILE)   // 391

__device__ uint4 g_a[(NMAX + 1) * 8];
__device__ uint4 g_b[(NMAX + 1) * 8];
__device__ uint4 g_anchor[(NMAX + 1) * 8];  // 0.1*norm*feat in fp16
__device__ float g_norm[NMAX];
__device__ int   g_deg[NMAX];
__device__ int   g_rowptr[NMAX + 1];        // padded-degree prefix
__device__ int   g_cursor[NMAX];
__device__ int   g_srcs[EPAD];
__device__ int   g_part[NTILE];

// ---------------------------------------------------------------- build ----

__global__ void k_zero(int n, int nthreads) {
    for (int i = blockIdx.x * blockDim.x + threadIdx.x; i < n; i += nthreads) {
        g_deg[i] = 0; g_cursor[i] = 0;
    }
}

__global__ void k_deg(const int* __restrict__ dst, int e, int nthreads) {
    for (int i = blockIdx.x * blockDim.x + threadIdx.x; i < e; i += nthreads)
        atomicAdd(&g_deg[dst[i]], 1);
}

__global__ void k_scan_part(int n) {
    __shared__ int sh[TILE];
    int t = threadIdx.x;
    int i = blockIdx.x * TILE + t;
    int d = (i < n) ? g_deg[i] : 0;
    sh[t] = (d + 3) & ~3;
    __syncthreads();
    for (int off = TILE >> 1; off > 0; off >>= 1) {
        if (t < off) sh[t] += sh[t + off];
        __syncthreads();
    }
    if (t == 0) g_part[blockIdx.x] = sh[0];
}

__global__ void k_scan_top(int nb) {
    __shared__ int sh[512];
    int t = threadIdx.x;
    int v = (t < nb) ? g_part[t] : 0;
    sh[t] = v;
    __syncthreads();
    for (int off = 1; off < 512; off <<= 1) {
        int x = (t >= off) ? sh[t - off] : 0;
        __syncthreads();
        sh[t] += x;
        __syncthreads();
    }
    if (t < nb) g_part[t] = sh[t] - v;
}

__global__ void k_scan_fin(int n) {
    __shared__ int sh[TILE];
    int t = threadIdx.x;
    int i = blockIdx.x * TILE + t;
    int d    = (i < n) ? g_deg[i] : 0;
    int dpad = (d + 3) & ~3;
    sh[t] = dpad;
    __syncthreads();
    for (int off = 1; off < TILE; off <<= 1) {
        int x = (t >= off) ? sh[t - off] : 0;
        __syncthreads();
        sh[t] += x;
        __syncthreads();
    }
    if (i < n) {
        g_rowptr[i] = sh[t] - dpad + g_part[blockIdx.x];
        g_norm[i]   = rsqrtf(fmaxf((float)d, 1.0f));
        if (i == n - 1) g_rowptr[n] = sh[t] + g_part[blockIdx.x];
    }
}

__global__ void k_fill(const int* __restrict__ src,
                       const int* __restrict__ dst, int e, int nthreads) {
    for (int i = blockIdx.x * blockDim.x + threadIdx.x; i < e; i += nthreads) {
        int d = dst[i];
        int pos = g_rowptr[d] + atomicAdd(&g_cursor[d], 1);
        g_srcs[pos] = src[i];
    }
}

__global__ void k_pad(int n, int nthreads) {
    for (int i = blockIdx.x * blockDim.x + threadIdx.x; i < n; i += nthreads) {
        int s  = g_rowptr[i] + g_deg[i];
        int e2 = g_rowptr[i + 1];
        for (int j = s; j < e2; ++j) g_srcs[j] = n;
    }
}

__global__ void k_init(const float* __restrict__ feat, int n, int nthreads) {
    int tot = (n + 1) * DF2;
    __half2* pa = reinterpret_cast<__half2*>(g_a);
    __half2* pb = reinterpret_cast<__half2*>(g_b);
    __half2* pn = reinterpret_cast<__half2*>(g_anchor);
    for (int i = blockIdx.x * blockDim.x + threadIdx.x; i < tot; i += nthreads) {
        int row = i >> 5;
        if (row < n) {
            float nm = g_norm[row];
            float2 f = reinterpret_cast<const float2*>(feat)[i];
            pa[i] = __floats2half2_rn(nm * f.x, nm * f.y);
            pn[i] = __floats2half2_rn(0.1f * nm * f.x, 0.1f * nm * f.y);
        } else {
            __half2 z = __floats2half2_rn(0.f, 0.f);
            pa[i] = z; pb[i] = z; pn[i] = z;
        }
    }
}

// ----------------------------------------------------------------- loop ----

__device__ __forceinline__ void acc_row(const uint4& r, float* acc) {
    const __half2* h = reinterpret_cast<const __half2*>(&r);
    #pragma unroll
    for (int j = 0; j < 4; ++j) {
        float2 w = __half22float2(h[j]);
        acc[2 * j]     += w.x;
        acc[2 * j + 1] += w.y;
    }
}

// Single-wave: each warp strides over nodes. SIMT-4 gather (one LDG.128 =
// four 128B fp16 rows, 8 lanes per row), fp32 partials, xor-shuffle fold.
__global__ void __launch_bounds__(256) k_prop(
        const float* __restrict__ feat, float* __restrict__ out,
        int n, int flip, int last, int warps_total) {
    int wid0 = (blockIdx.x * blockDim.x + threadIdx.x) >> 5;
    int lane = threadIdx.x & 31;
    int slot = lane >> 3;
    int oct  = lane & 7;

    const uint4* gin  = flip ? g_b : g_a;
    uint4*       gout = flip ? g_a : g_b;

    for (int v = wid0; v < n; v += warps_total) {
        int idx = __ldg(&g_rowptr[v]);
        int end = __ldg(&g_rowptr[v + 1]);   // padded to multiple of 4

        float acc[8];
        #pragma unroll
        for (int j = 0; j < 8; ++j) acc[j] = 0.f;

        for (; idx + 8 <= end; idx += 8) {
            int s0 = __ldg(&g_srcs[idx + slot]);
            int s1 = __ldg(&g_srcs[idx + 4 + slot]);
            uint4 r0 = gin[s0 * 8 + oct];
            uint4 r1 = gin[s1 * 8 + oct];
            acc_row(r0, acc);
            acc_row(r1, acc);
        }
        if (idx < end) {
            int s0 = __ldg(&g_srcs[idx + slot]);
            uint4 r0 = gin[s0 * 8 + oct];
            acc_row(r0, acc);
        }

        #pragma unroll
        for (int j = 0; j < 8; ++j) {
            acc[j] += __shfl_xor_sync(0xffffffff, acc[j], 8);
            acc[j] += __shfl_xor_sync(0xffffffff, acc[j], 16);
        }

        float nm = __ldg(&g_norm[v]);

        if (!last) {
            if (lane < 8) {
                float c1 = 0.9f * nm * nm;
                uint4 an = g_anchor[v * 8 + oct];
                const __half2* ah = reinterpret_cast<const __half2*>(&an);
                uint4 o;
                __half2* oh = reinterpret_cast<__half2*>(&o);
                #pragma unroll
                for (int j = 0; j < 4; ++j) {
                    float2 a2 = __half22float2(ah[j]);
                    oh[j] = __floats2half2_rn(c1 * acc[2 * j]     + a2.x,
                                              c1 * acc[2 * j + 1] + a2.y);
                }
                gout[v * 8 + oct] = o;
            }
        } else {
            if (lane < 8) {
                float c1 = 0.9f * nm;
                const float4* fr = reinterpret_cast<const float4*>(feat + v * DF);
                float4* orow = reinterpret_cast<float4*>(out + v * DF);
                float4 f0 = fr[oct * 2];
                float4 f1 = fr[oct * 2 + 1];
                float4 o0, o1;
                o0.x = c1 * acc[0] + 0.1f * f0.x;
                o0.y = c1 * acc[1] + 0.1f * f0.y;
                o0.z = c1 * acc[2] + 0.1f * f0.z;
                o0.w = c1 * acc[3] + 0.1f * f0.w;
                o1.x = c1 * acc[4] + 0.1f * f1.x;
                o1.y = c1 * acc[5] + 0.1f * f1.y;
                o1.z = c1 * acc[6] + 0.1f * f1.z;
                o1.w = c1 * acc[7] + 0.1f * f1.w;
                orow[oct * 2]     = o0;
                orow[oct * 2 + 1] = o1;
            }
        }
    }
}

// ---------------------------------------------------------------- launch ----

extern "C" void kernel_launch(void* const* d_in, const int* in_sizes, int n_in,
                              void* d_out, int out_size) {
    const float* feat = (const float*)d_in[0];
    const int*   src  = (const int*)d_in[1];
    const int*   dst  = (const int*)d_in[2];
    float*       out  = (float*)d_out;

    int n = in_sizes[0] / DF;   // 100000
    int e = in_sizes[1];        // 1000000

    const int T = 256;
    int nb = (n + TILE - 1) / TILE;

    // Single-wave grid size for streaming kernels.
    int dev = 0;
    cudaGetDevice(&dev);
    int sm_count = 0;
    cudaDeviceGetAttribute(&sm_count, cudaDevAttrMultiProcessorCount, dev);
    int occ = 0;
    cudaOccupancyMaxActiveBlocksPerMultiprocessor(&occ, k_prop, T, 0);
    if (occ < 1) occ = 1;
    int nblocks = sm_count * occ;
    int nthreads = nblocks * T;
    int warps_total = nthreads >> 5;

    // CSR build with 4-padded segments (grid-stride, single wave)
    k_zero<<<nblocks, T>>>(n, nthreads);
    k_deg<<<nblocks, T>>>(dst, e, nthreads);
    k_scan_part<<<nb, TILE>>>(n);
    k_scan_top<<<1, 512>>>(nb);
    k_scan_fin<<<nb, TILE>>>(n);
    k_fill<<<nblocks, T>>>(src, dst, e, nthreads);
    k_pad<<<nblocks, T>>>(n, nthreads);
    k_init<<<nblocks, T>>>(feat, n, nthreads);

    // Propagation: ping-pong g_a <-> g_b, final iter writes d_out (fp32).
    for (int t = 0; t < KITER; ++t) {
        int flip = t & 1;
        int last = (t == KITER - 1);
        k_prop<<<nblocks, T>>>(feat, out, n, flip, last, warps_total);
    }
}